// round 8
// baseline (speedup 1.0000x reference)
#include <cuda_runtime.h>
#include <math.h>

// DehLoss: O(n^2) pairwise Gaussian-kernel loss, n = 8192.
// R_i = g1_i + log(y_i), h = 1.3*n^-0.2, dr_ij = (R_i - R_j)/h
// Dk_j = sum_i d_i*phi(dr_ij);  LP_j = sum_i L_i*ndtr(dr_ij), L_i = exp(g2_i-g1_i)
// out = -(S1+S2+S3+S4)
//
// R8: columns+rows processed in SORTED R order (single-block bitonic sort,
// deterministic). (j-block x chunk) tiles fully outside |dr|<=6 are skipped
// analytically: Dk partial = 0, LP partial = +-0.5 * chunkLsum (error <1e-8
// per pair). Pair inner loop byte-identical to R6/R7. S1+S2 and Lsum computed
// in the sort kernel. 3 launches.

#define N      8192
#define SPLITS 32
#define CHUNK  (N / SPLITS)   // 256 columns per split
#define JT     128
#define GX     (N / JT)       // 64 j-blocks
#define RB     32             // reduce blocks
#define BAND   6.0f           // |dr| cutoff: phi(6)=6e-9, 1-ndtr(6)=1e-9

typedef unsigned long long u64;

__device__ float4 g_A[N / 2];     // sorted {Rh_2m, Rh_2m+1, d_2m, d_2m+1}
__device__ float2 g_Lp[N / 2];    // sorted {L_2m, L_2m+1}
__device__ float  g_rowRh[N];     // compacted (sorted) Rh_j for d_j=1
__device__ int    g_M;            // number of compacted rows
__device__ int    g_ctr;          // last-block counter for reduce
__device__ float  g_cRmin[SPLITS], g_cRmax[SPLITS], g_cLs[SPLITS];
__device__ double g_S12;          // sum_j d_j*(g2_j - R_j)
__device__ double g_Lsumd;        // sum_i L_i
__device__ float  g_partDk[SPLITS * N];
__device__ float  g_partLP[SPLITS * N];
__device__ double g_bsum[RB];

__device__ __forceinline__ float ex2f_(float x) {
    float r; asm("ex2.approx.ftz.f32 %0, %1;" : "=f"(r) : "f"(x)); return r;
}
__device__ __forceinline__ float rcpf_(float x) {
    float r; asm("rcp.approx.ftz.f32 %0, %1;" : "=f"(r) : "f"(x)); return r;
}
__device__ __forceinline__ u64 pk2(float lo, float hi) {
    u64 r; asm("mov.b64 %0, {%1, %2};" : "=l"(r) : "f"(lo), "f"(hi)); return r;
}
__device__ __forceinline__ void upk2(u64 v, float& lo, float& hi) {
    asm("mov.b64 {%0, %1}, %2;" : "=f"(lo), "=f"(hi) : "l"(v));
}
__device__ __forceinline__ u64 fma2_(u64 a, u64 b, u64 c) {
    u64 d; asm("fma.rn.f32x2 %0, %1, %2, %3;" : "=l"(d) : "l"(a), "l"(b), "l"(c)); return d;
}
__device__ __forceinline__ u64 mul2_(u64 a, u64 b) {
    u64 d; asm("mul.rn.f32x2 %0, %1, %2;" : "=l"(d) : "l"(a), "l"(b)); return d;
}
__device__ __forceinline__ u64 add2_(u64 a, u64 b) {
    u64 d; asm("add.rn.f32x2 %0, %1, %2;" : "=l"(d) : "l"(a), "l"(b)); return d;
}

// One block: compute per-i values, bitonic-sort by Rh (payload L, flag in
// sign), compact rows, chunk stats, S1+S2 and Lsum reductions. Deterministic.
__global__ void __launch_bounds__(1024) sortprep_kernel(const float* __restrict__ mz,
                                                        const float* __restrict__ y,
                                                        const float* __restrict__ delta,
                                                        float inv_h) {
    extern __shared__ float dynsm[];
    float* skey = dynsm;        // [N]
    float* sval = dynsm + N;    // [N]  |L| with sign bit = flag
    __shared__ int    cnt[1024];
    __shared__ double dred[1024];

    const int t = threadIdx.x;
    if (t == 0) g_ctr = 0;

    double s12 = 0.0, ls = 0.0;
    #pragma unroll
    for (int q = 0; q < 8; ++q) {
        int j = q * 1024 + t;
        float g1 = mz[2 * j], g2 = mz[2 * j + 1];
        float R  = g1 + logf(y[j]);
        float L  = expf(g2 - g1);
        int   f  = delta[j] > 0.5f;
        s12 += (double)((f ? 1.0f : 0.0f) * (g2 - R));
        ls  += (double)L;
        skey[j] = R * inv_h;
        sval[j] = f ? -L : L;
    }
    __syncthreads();

    // bitonic sort ascending by key, payload follows
    for (unsigned k = 2; k <= (unsigned)N; k <<= 1) {
        for (unsigned jj = k >> 1; jj > 0; jj >>= 1) {
            #pragma unroll
            for (int q = 0; q < 8; ++q) {
                unsigned i = q * 1024 + t;
                unsigned l = i ^ jj;
                if (l > i) {
                    bool asc = ((i & k) == 0);
                    float ka = skey[i], kb = skey[l];
                    if ((ka > kb) == asc) {
                        skey[i] = kb; skey[l] = ka;
                        float va = sval[i], vb = sval[l];
                        sval[i] = vb; sval[l] = va;
                    }
                }
            }
            __syncthreads();
        }
    }

    // chunk stats
    if (t < SPLITS) {
        g_cRmin[t] = skey[t * CHUNK];
        g_cRmax[t] = skey[t * CHUNK + CHUNK - 1];
    }
    {   // chunk L sums: warp w handles chunk w (fixed-order shfl tree)
        int w = t >> 5, lane = t & 31;
        float s = 0.0f;
        for (int e = lane; e < CHUNK; e += 32) s += fabsf(sval[w * CHUNK + e]);
        #pragma unroll
        for (int o = 16; o > 0; o >>= 1) s += __shfl_down_sync(0xFFFFFFFFu, s, o);
        if (lane == 0) g_cLs[w] = s;
    }

    // compaction scan over sorted flags + pack outputs
    const int base = t * 8;
    float kR[8], vL[8]; int flags[8]; int c = 0;
    #pragma unroll
    for (int q = 0; q < 8; ++q) {
        float v = sval[base + q];
        kR[q] = skey[base + q];
        flags[q] = v < 0.0f;
        vL[q] = fabsf(v);
        c += flags[q];
    }
    cnt[t] = c;
    __syncthreads();
    for (int off = 1; off < 1024; off <<= 1) {
        int v = (t >= off) ? cnt[t - off] : 0;
        __syncthreads();
        cnt[t] += v;
        __syncthreads();
    }
    int pos = cnt[t] - c;
    #pragma unroll
    for (int q = 0; q < 8; ++q) {
        if (flags[q]) g_rowRh[pos++] = kR[q];
        if (q & 1) {
            float4 a; a.x = kR[q - 1]; a.y = kR[q];
            a.z = (float)flags[q - 1]; a.w = (float)flags[q];
            g_A[(base + q) >> 1] = a;
            g_Lp[(base + q) >> 1] = make_float2(vL[q - 1], vL[q]);
        }
    }
    if (t == 1023) g_M = cnt[1023];

    // S12 and Lsum double reductions (fixed-order trees)
    dred[t] = s12;
    __syncthreads();
    for (int s = 512; s > 0; s >>= 1) { if (t < s) dred[t] += dred[t + s]; __syncthreads(); }
    if (t == 0) g_S12 = dred[0];
    __syncthreads();
    dred[t] = ls;
    __syncthreads();
    for (int s = 512; s > 0; s >>= 1) { if (t < s) dred[t] += dred[t + s]; __syncthreads(); }
    if (t == 0) g_Lsumd = dred[0];
}

__global__ void __launch_bounds__(JT) pair_kernel() {
    __shared__ float4 shA[CHUNK / 2];
    __shared__ float2 shL[CHUNK / 2];
    const int M = g_M;
    const int c0 = blockIdx.x * JT;
    if (c0 >= M) return;

    const int c  = c0 + threadIdx.x;
    const int cc = min(c, M - 1);
    const int s  = blockIdx.y;

    // band skip: tile fully outside |dr| <= BAND -> analytic contribution
    {
        const float Rlo = g_rowRh[c0];
        const float Rhi = g_rowRh[min(c0 + JT - 1, M - 1)];
        const float cmin = g_cRmin[s], cmax = g_cRmax[s];
        if (cmin > Rhi + BAND) {           // all dr >> 0: ndtr=1, phi=0
            if (c < M) { g_partDk[s * N + c] = 0.0f; g_partLP[s * N + c] =  0.5f * g_cLs[s]; }
            return;
        }
        if (cmax < Rlo - BAND) {           // all dr << 0: ndtr=0, phi=0
            if (c < M) { g_partDk[s * N + c] = 0.0f; g_partLP[s * N + c] = -0.5f * g_cLs[s]; }
            return;
        }
    }

    const int base2 = s * (CHUNK / 2);
    for (int k = threadIdx.x; k < CHUNK / 2; k += JT) {
        shA[k] = g_A[base2 + k];
        shL[k] = g_Lp[base2 + k];
    }
    const float Rhj = g_rowRh[cc];
    __syncthreads();

    // C1 = -0.5*log2(e), C2 = log2(1/sqrt(2*pi)); AS 26.2.16 coeffs negated.
    const u64 nRhj2 = pk2(-Rhj, -Rhj);
    const u64 C1_2  = pk2(-0.72134752044448170f, -0.72134752044448170f);
    const u64 C2_2  = pk2(-1.32574806473615923f, -1.32574806473615923f);
    const u64 PP2   = pk2(0.33267f, 0.33267f);
    const u64 ONE2  = pk2(1.0f, 1.0f);
    const u64 HALF2 = pk2(0.5f, 0.5f);
    const u64 NA1_2 = pk2(-0.4361836f, -0.4361836f);
    const u64 NA2_2 = pk2( 0.1201676f,  0.1201676f);
    const u64 NA3_2 = pk2(-0.9372980f, -0.9372980f);
    const u64 AMSK  = 0x7FFFFFFF7FFFFFFFULL;
    const u64 SMSK  = 0x8000000080000000ULL;

    u64 dk2 = 0ULL, lp2 = 0ULL;

    #pragma unroll 8
    for (int k = 0; k < CHUNK / 2; ++k) {
        float4 a = shA[k];
        float2 L = shL[k];
        u64 Rh2 = pk2(a.x, a.y);
        u64 d2  = pk2(a.z, a.w);
        u64 L2  = pk2(L.x, L.y);

        u64 dr2 = add2_(Rh2, nRhj2);               // (R_i - R_j)/h, 2 lanes
        u64 e2  = fma2_(mul2_(dr2, C1_2), dr2, C2_2);
        float elo, ehi; upk2(e2, elo, ehi);
        u64 phi2 = pk2(ex2f_(elo), ex2f_(ehi));    // normal pdf, both lanes
        dk2 = fma2_(d2, phi2, dk2);

        u64 den2 = fma2_(dr2 & AMSK, PP2, ONE2);   // 1 + p|dr|
        float dlo, dhi; upk2(den2, dlo, dhi);
        float rr = rcpf_(dlo * dhi);               // one rcp, both lanes
        u64 t2 = pk2(rr * dhi, rr * dlo);          // {1/dlo, 1/dhi}

        u64 p2 = fma2_(t2, NA3_2, NA2_2);          // -poly3(t), Horner
        p2 = fma2_(t2, p2, NA1_2);
        p2 = mul2_(t2, p2);
        u64 u2 = fma2_(phi2, p2, HALF2);           // 0.5 - q >= 0
        u64 v2 = u2 | (dr2 & SMSK);                // ndtr(dr) - 0.5
        lp2 = fma2_(L2, v2, lp2);
    }

    float dka, dkb, lpa, lpb;
    upk2(dk2, dka, dkb);
    upk2(lp2, lpa, lpb);
    if (c < M) {
        g_partDk[s * N + c] = dka + dkb;
        g_partLP[s * N + c] = lpa + lpb;
    }
}

// Epilogue: logs over compacted columns, 32 blocks; last block combines.
__global__ void __launch_bounds__(256) reduce_kernel(float h, float* __restrict__ out) {
    __shared__ double red[256];
    __shared__ int    lastFlag;
    const int t   = threadIdx.x;
    const int gid = blockIdx.x * 256 + t;
    const int M   = g_M;
    const float Lsum   = (float)g_Lsumd;
    const float inv_nh = 1.0f / ((float)N * h);
    const float invn   = 1.0f / (float)N;

    double acc = 0.0;
    if (gid < M) {
        float dk = 0.0f, lp = 0.0f;
        #pragma unroll
        for (int s2 = 0; s2 < SPLITS; ++s2) {
            dk += g_partDk[s2 * N + gid];
            lp += g_partLP[s2 * N + gid];
        }
        float Dk = dk * inv_nh;
        float LP = (lp + 0.5f * Lsum) * invn;
        acc = (double)(logf(Dk + 1e-15f) - logf(LP + 1e-15f));
    }
    red[t] = acc;
    __syncthreads();
    for (int s = 128; s > 0; s >>= 1) {
        if (t < s) red[t] += red[t + s];
        __syncthreads();
    }
    if (t == 0) g_bsum[blockIdx.x] = red[0];

    __threadfence();
    if (t == 0) {
        int prev = atomicAdd(&g_ctr, 1);
        lastFlag = (prev == RB - 1);
    }
    __syncthreads();
    if (!lastFlag) return;

    if (t < 32) {
        double v = g_bsum[t];
        #pragma unroll
        for (int s = 16; s > 0; s >>= 1)
            v += __shfl_down_sync(0xFFFFFFFFu, v, s);
        if (t == 0) out[0] = (float)(-(v + g_S12) / (double)N);
    }
}

extern "C" void kernel_launch(void* const* d_in, const int* in_sizes, int n_in,
                              void* d_out, int out_size) {
    const float* mz    = (const float*)d_in[0];
    const float* y     = (const float*)d_in[1];
    const float* delta = (const float*)d_in[2];
    float* out = (float*)d_out;

    const double hd = 1.3 * pow((double)N, -0.2);
    const int smem = 2 * N * (int)sizeof(float);

    cudaFuncSetAttribute(sortprep_kernel,
                         cudaFuncAttributeMaxDynamicSharedMemorySize, smem);
    sortprep_kernel<<<1, 1024, smem>>>(mz, y, delta, (float)(1.0 / hd));
    dim3 grid(GX, SPLITS);
    pair_kernel<<<grid, JT>>>();
    reduce_kernel<<<RB, 256>>>((float)hd, out);
}

// round 9
// speedup vs baseline: 2.6919x; 2.6919x over previous
#include <cuda_runtime.h>
#include <math.h>

// DehLoss: O(n^2) pairwise Gaussian-kernel loss, n = 8192.
// R_i = g1_i + log(y_i), h = 1.3*n^-0.2, dr_ij = (R_i - R_j)/h
// Dk_j = sum_i d_i*phi(dr_ij);  LP_j = sum_i L_i*ndtr(dr_ij), L_i = exp(g2_i-g1_i)
// out = -(S1+S2+S3+S4)
//
// R9: band pruning via 64-bucket deterministic binning (NOT bitonic sort —
// R8 showed that costs 113us). Block b of the bucket kernel redundantly
// counts elements in buckets < b for its stable base offsets; within-bucket
// order is original index order -> fully deterministic. Pair kernel computes
// chunk/row min/max + chunk Lsum from its own smem tile (one extra shfl
// reduce, same single barrier) and skips tiles with |dr| > 6 analytically:
// Dk partial = 0, LP partial = +-0.5*chunkLsum (phi(6)=6e-9, tail 1e-9).
// Pair inner loop byte-identical to R6/R7. 4 launches.

#define N      8192
#define SPLITS 32
#define CHUNK  (N / SPLITS)   // 256 columns per split
#define JT     128
#define GX     (N / JT)       // 64 j-blocks
#define RB     32             // reduce blocks
#define PB     32             // prep blocks
#define PT     256
#define NB     64             // buckets
#define BAND   6.0f

typedef unsigned long long u64;

__device__ float  g_key[N];       // Rh per element (original order)
__device__ float  g_val[N];       // L with sign bit = delta flag
__device__ float  g_skey[N];      // bucket-ordered Rh
__device__ float  g_sval[N];      // bucket-ordered +-L
__device__ float  g_rowRh[N];     // bucket-ordered Rh of flagged rows
__device__ int    g_M;            // number of flagged rows
__device__ int    g_ctr;          // last-block counter for reduce
__device__ float  g_minp[PB], g_maxp[PB];
__device__ double g_s12p[PB], g_lsp[PB];
__device__ float  g_partDk[SPLITS * N];
__device__ float  g_partLP[SPLITS * N];
__device__ double g_bsum[RB];

__device__ __forceinline__ float ex2f_(float x) {
    float r; asm("ex2.approx.ftz.f32 %0, %1;" : "=f"(r) : "f"(x)); return r;
}
__device__ __forceinline__ float rcpf_(float x) {
    float r; asm("rcp.approx.ftz.f32 %0, %1;" : "=f"(r) : "f"(x)); return r;
}
__device__ __forceinline__ u64 pk2(float lo, float hi) {
    u64 r; asm("mov.b64 %0, {%1, %2};" : "=l"(r) : "f"(lo), "f"(hi)); return r;
}
__device__ __forceinline__ void upk2(u64 v, float& lo, float& hi) {
    asm("mov.b64 {%0, %1}, %2;" : "=f"(lo), "=f"(hi) : "l"(v));
}
__device__ __forceinline__ u64 fma2_(u64 a, u64 b, u64 c) {
    u64 d; asm("fma.rn.f32x2 %0, %1, %2, %3;" : "=l"(d) : "l"(a), "l"(b), "l"(c)); return d;
}
__device__ __forceinline__ u64 mul2_(u64 a, u64 b) {
    u64 d; asm("mul.rn.f32x2 %0, %1, %2;" : "=l"(d) : "l"(a), "l"(b)); return d;
}
__device__ __forceinline__ u64 add2_(u64 a, u64 b) {
    u64 d; asm("add.rn.f32x2 %0, %1, %2;" : "=l"(d) : "l"(a), "l"(b)); return d;
}

// A: per-element values + per-block min/max/S12/Lsum partials.
__global__ void __launch_bounds__(PT) prep_kernel(const float* __restrict__ mz,
                                                  const float* __restrict__ y,
                                                  const float* __restrict__ delta,
                                                  float inv_h) {
    __shared__ float  fred[PT];
    __shared__ double dred[PT];
    const int b = blockIdx.x, t = threadIdx.x;
    const int j = b * PT + t;
    if (b == 0 && t == 0) g_ctr = 0;

    float g1 = mz[2 * j], g2 = mz[2 * j + 1];
    float R  = g1 + logf(y[j]);
    float Rh = R * inv_h;
    float L  = expf(g2 - g1);
    int   f  = delta[j] > 0.5f;
    g_key[j] = Rh;
    g_val[j] = f ? -L : L;

    // min
    fred[t] = Rh; __syncthreads();
    for (int s = PT / 2; s > 0; s >>= 1) { if (t < s) fred[t] = fminf(fred[t], fred[t + s]); __syncthreads(); }
    if (t == 0) g_minp[b] = fred[0];
    __syncthreads();
    // max
    fred[t] = Rh; __syncthreads();
    for (int s = PT / 2; s > 0; s >>= 1) { if (t < s) fred[t] = fmaxf(fred[t], fred[t + s]); __syncthreads(); }
    if (t == 0) g_maxp[b] = fred[0];
    __syncthreads();
    // S12 partial: d*(g2 - R)
    dred[t] = (double)((f ? 1.0f : 0.0f) * (g2 - R)); __syncthreads();
    for (int s = PT / 2; s > 0; s >>= 1) { if (t < s) dred[t] += dred[t + s]; __syncthreads(); }
    if (t == 0) g_s12p[b] = dred[0];
    __syncthreads();
    // Lsum partial
    dred[t] = (double)L; __syncthreads();
    for (int s = PT / 2; s > 0; s >>= 1) { if (t < s) dred[t] += dred[t + s]; __syncthreads(); }
    if (t == 0) g_lsp[b] = dred[0];
}

// B: 64 blocks, block b = bucket b. Stable deterministic scatter of the full
// set into g_skey/g_sval and of the flagged subset into g_rowRh.
__global__ void __launch_bounds__(PT) bucket_kernel() {
    __shared__ int sred[PT];
    __shared__ int wA[PT / 32], wF[PT / 32];
    const int b = blockIdx.x, t = threadIdx.x;
    const int lane = t & 31, wi = t >> 5;

    float lo = g_minp[0], hi = g_maxp[0];
    #pragma unroll
    for (int q = 1; q < PB; ++q) { lo = fminf(lo, g_minp[q]); hi = fmaxf(hi, g_maxp[q]); }
    const float scale = (float)NB / fmaxf(hi - lo, 1e-20f);

    // pass1: base offsets = counts in buckets < b (and flagged counts)
    int cA = 0, cF = 0, cT = 0;
    for (int k = t; k < N; k += PT) {
        float key = g_key[k];
        int bk = (int)fminf(fmaxf((key - lo) * scale, 0.0f), (float)(NB - 1));
        int fl = g_val[k] < 0.0f;
        cA += (bk < b);
        cF += (bk < b) & fl;
        cT += fl;
    }
    sred[t] = cA; __syncthreads();
    for (int s = PT / 2; s > 0; s >>= 1) { if (t < s) sred[t] += sred[t + s]; __syncthreads(); }
    int baseA = sred[0];
    __syncthreads();
    sred[t] = cF; __syncthreads();
    for (int s = PT / 2; s > 0; s >>= 1) { if (t < s) sred[t] += sred[t + s]; __syncthreads(); }
    int baseF = sred[0];
    __syncthreads();
    if (b == NB - 1) {   // total flagged rows (block-uniform branch)
        sred[t] = cT; __syncthreads();
        for (int s = PT / 2; s > 0; s >>= 1) { if (t < s) sred[t] += sred[t + s]; __syncthreads(); }
        if (t == 0) g_M = sred[0];
        __syncthreads();
    }

    // pass2: stable scatter wave by wave (index order preserved)
    for (int w = 0; w < N / PT; ++w) {
        int k = w * PT + t;
        float key = g_key[k], val = g_val[k];
        int bk = (int)fminf(fmaxf((key - lo) * scale, 0.0f), (float)(NB - 1));
        bool inb = (bk == b);
        bool fl  = inb && (val < 0.0f);
        unsigned balA = __ballot_sync(0xFFFFFFFFu, inb);
        unsigned balF = __ballot_sync(0xFFFFFFFFu, fl);
        if (lane == 0) { wA[wi] = __popc(balA); wF[wi] = __popc(balF); }
        __syncthreads();
        int offA = 0, offF = 0, totA = 0, totF = 0;
        #pragma unroll
        for (int q = 0; q < PT / 32; ++q) {
            totA += wA[q]; totF += wF[q];
            if (q < wi) { offA += wA[q]; offF += wF[q]; }
        }
        if (inb) {
            int p = baseA + offA + __popc(balA & ((1u << lane) - 1u));
            g_skey[p] = key; g_sval[p] = val;
        }
        if (fl) {
            int p = baseF + offF + __popc(balF & ((1u << lane) - 1u));
            g_rowRh[p] = key;
        }
        baseA += totA; baseF += totF;
        __syncthreads();
    }
}

__global__ void __launch_bounds__(JT) pair_kernel() {
    __shared__ float4 shA[CHUNK / 2];
    __shared__ float2 shL[CHUNK / 2];
    __shared__ float  wred[5][JT / 32];
    const int M = g_M;
    const int c0 = blockIdx.x * JT;
    if (c0 >= M) return;

    const int c  = c0 + threadIdx.x;
    const int cc = min(c, M - 1);
    const int s  = blockIdx.y;
    const float Rhj = g_rowRh[cc];

    // fill smem tile + per-thread chunk stats
    float cmin = 1e30f, cmax = -1e30f, cls = 0.0f;
    const int cbase = s * CHUNK;
    for (int k = threadIdx.x; k < CHUNK / 2; k += JT) {
        float kx = g_skey[cbase + 2 * k], ky = g_skey[cbase + 2 * k + 1];
        float vx = g_sval[cbase + 2 * k], vy = g_sval[cbase + 2 * k + 1];
        float ax = fabsf(vx), ay = fabsf(vy);
        shA[k] = make_float4(kx, ky, vx < 0.0f ? 1.0f : 0.0f, vy < 0.0f ? 1.0f : 0.0f);
        shL[k] = make_float2(ax, ay);
        cmin = fminf(cmin, fminf(kx, ky));
        cmax = fmaxf(cmax, fmaxf(kx, ky));
        cls += ax + ay;
    }
    float rmin = Rhj, rmax = Rhj;
    #pragma unroll
    for (int o = 16; o > 0; o >>= 1) {
        cmin = fminf(cmin, __shfl_down_sync(0xFFFFFFFFu, cmin, o));
        cmax = fmaxf(cmax, __shfl_down_sync(0xFFFFFFFFu, cmax, o));
        cls += __shfl_down_sync(0xFFFFFFFFu, cls, o);
        rmin = fminf(rmin, __shfl_down_sync(0xFFFFFFFFu, rmin, o));
        rmax = fmaxf(rmax, __shfl_down_sync(0xFFFFFFFFu, rmax, o));
    }
    {
        int w = threadIdx.x >> 5, lane = threadIdx.x & 31;
        if (lane == 0) {
            wred[0][w] = cmin; wred[1][w] = cmax; wred[2][w] = cls;
            wred[3][w] = rmin; wred[4][w] = rmax;
        }
    }
    __syncthreads();   // also orders the smem tile for the loop below
    cmin = wred[0][0]; cmax = wred[1][0]; cls = wred[2][0];
    rmin = wred[3][0]; rmax = wred[4][0];
    #pragma unroll
    for (int q = 1; q < JT / 32; ++q) {
        cmin = fminf(cmin, wred[0][q]); cmax = fmaxf(cmax, wred[1][q]); cls += wred[2][q];
        rmin = fminf(rmin, wred[3][q]); rmax = fmaxf(rmax, wred[4][q]);
    }

    // band skip: tile fully outside |dr| <= BAND -> analytic contribution
    if (cmin > rmax + BAND) {     // all dr >> 0: ndtr=1, phi=0
        if (c < M) { g_partDk[s * N + c] = 0.0f; g_partLP[s * N + c] =  0.5f * cls; }
        return;
    }
    if (cmax < rmin - BAND) {     // all dr << 0: ndtr=0, phi=0
        if (c < M) { g_partDk[s * N + c] = 0.0f; g_partLP[s * N + c] = -0.5f * cls; }
        return;
    }

    // C1 = -0.5*log2(e), C2 = log2(1/sqrt(2*pi)); AS 26.2.16 coeffs negated.
    const u64 nRhj2 = pk2(-Rhj, -Rhj);
    const u64 C1_2  = pk2(-0.72134752044448170f, -0.72134752044448170f);
    const u64 C2_2  = pk2(-1.32574806473615923f, -1.32574806473615923f);
    const u64 PP2   = pk2(0.33267f, 0.33267f);
    const u64 ONE2  = pk2(1.0f, 1.0f);
    const u64 HALF2 = pk2(0.5f, 0.5f);
    const u64 NA1_2 = pk2(-0.4361836f, -0.4361836f);
    const u64 NA2_2 = pk2( 0.1201676f,  0.1201676f);
    const u64 NA3_2 = pk2(-0.9372980f, -0.9372980f);
    const u64 AMSK  = 0x7FFFFFFF7FFFFFFFULL;
    const u64 SMSK  = 0x8000000080000000ULL;

    u64 dk2 = 0ULL, lp2 = 0ULL;

    #pragma unroll 8
    for (int k = 0; k < CHUNK / 2; ++k) {
        float4 a = shA[k];
        float2 L = shL[k];
        u64 Rh2 = pk2(a.x, a.y);
        u64 d2  = pk2(a.z, a.w);
        u64 L2  = pk2(L.x, L.y);

        u64 dr2 = add2_(Rh2, nRhj2);               // (R_i - R_j)/h, 2 lanes
        u64 e2  = fma2_(mul2_(dr2, C1_2), dr2, C2_2);
        float elo, ehi; upk2(e2, elo, ehi);
        u64 phi2 = pk2(ex2f_(elo), ex2f_(ehi));    // normal pdf, both lanes
        dk2 = fma2_(d2, phi2, dk2);

        u64 den2 = fma2_(dr2 & AMSK, PP2, ONE2);   // 1 + p|dr|
        float dlo, dhi; upk2(den2, dlo, dhi);
        float rr = rcpf_(dlo * dhi);               // one rcp, both lanes
        u64 t2 = pk2(rr * dhi, rr * dlo);          // {1/dlo, 1/dhi}

        u64 p2 = fma2_(t2, NA3_2, NA2_2);          // -poly3(t), Horner
        p2 = fma2_(t2, p2, NA1_2);
        p2 = mul2_(t2, p2);
        u64 u2 = fma2_(phi2, p2, HALF2);           // 0.5 - q >= 0
        u64 v2 = u2 | (dr2 & SMSK);                // ndtr(dr) - 0.5
        lp2 = fma2_(L2, v2, lp2);
    }

    float dka, dkb, lpa, lpb;
    upk2(dk2, dka, dkb);
    upk2(lp2, lpa, lpb);
    if (c < M) {
        g_partDk[s * N + c] = dka + dkb;
        g_partLP[s * N + c] = lpa + lpb;
    }
}

// Epilogue: logs over compacted columns, 32 blocks; last block combines.
__global__ void __launch_bounds__(256) reduce_kernel(float h, float* __restrict__ out) {
    __shared__ double red[256];
    __shared__ int    lastFlag;
    const int t   = threadIdx.x;
    const int gid = blockIdx.x * 256 + t;
    const int M   = g_M;

    double lsd = 0.0;
    #pragma unroll
    for (int q = 0; q < PB; ++q) lsd += g_lsp[q];
    const float Lsum   = (float)lsd;
    const float inv_nh = 1.0f / ((float)N * h);
    const float invn   = 1.0f / (float)N;

    double acc = 0.0;
    if (gid < M) {
        float dk = 0.0f, lp = 0.0f;
        #pragma unroll
        for (int s2 = 0; s2 < SPLITS; ++s2) {
            dk += g_partDk[s2 * N + gid];
            lp += g_partLP[s2 * N + gid];
        }
        float Dk = dk * inv_nh;
        float LP = (lp + 0.5f * Lsum) * invn;
        acc = (double)(logf(Dk + 1e-15f) - logf(LP + 1e-15f));
    }
    red[t] = acc;
    __syncthreads();
    for (int s = 128; s > 0; s >>= 1) {
        if (t < s) red[t] += red[t + s];
        __syncthreads();
    }
    if (t == 0) g_bsum[blockIdx.x] = red[0];

    __threadfence();
    if (t == 0) {
        int prev = atomicAdd(&g_ctr, 1);
        lastFlag = (prev == RB - 1);
    }
    __syncthreads();
    if (!lastFlag) return;

    if (t < 32) {
        double v = g_bsum[t];
        #pragma unroll
        for (int s = 16; s > 0; s >>= 1)
            v += __shfl_down_sync(0xFFFFFFFFu, v, s);
        if (t == 0) {
            double s12 = 0.0;
            #pragma unroll
            for (int q = 0; q < PB; ++q) s12 += g_s12p[q];
            out[0] = (float)(-(v + s12) / (double)N);
        }
    }
}

extern "C" void kernel_launch(void* const* d_in, const int* in_sizes, int n_in,
                              void* d_out, int out_size) {
    const float* mz    = (const float*)d_in[0];
    const float* y     = (const float*)d_in[1];
    const float* delta = (const float*)d_in[2];
    float* out = (float*)d_out;

    const double hd = 1.3 * pow((double)N, -0.2);

    prep_kernel<<<PB, PT>>>(mz, y, delta, (float)(1.0 / hd));
    bucket_kernel<<<NB, PT>>>();
    dim3 grid(GX, SPLITS);
    pair_kernel<<<grid, JT>>>();
    reduce_kernel<<<RB, 256>>>((float)hd, out);
}